// round 2
// baseline (speedup 1.0000x reference)
#include <cuda_runtime.h>
#include <cuda_fp16.h>

#define NN 100000
#define NE 3200000
#define NG 1000

// ---------------- scratch (device globals) ----------------
__device__ __align__(16) __half g_msg1[NN * 16];
__device__ __align__(16) float  g_root1[NN * 16];
__device__ __align__(16) float  g_h1[NN * 16];
__device__ __align__(16) __half g_msg2[NN * 32];
__device__ __align__(16) float  g_root2[NN * 32];
__device__ __align__(16) float  g_h2[NN * 32];
__device__ __align__(16) __half g_msg3[NN * 32];
__device__ __align__(16) float  g_root3[NN * 32];
__device__ __align__(16) float  g_pooled[NG * 32];
__device__ int g_cnt[NN];
__device__ int g_rowptr[NN + 1];
__device__ int g_wptr[NN];
__device__ int g_srcs[NE];
__device__ int g_ei64;
__device__ int g_b64;

// ---------------- helpers ----------------
__device__ __forceinline__ void red4(float* addr, float4 v) {
    asm volatile("red.global.add.v4.f32 [%0], {%1,%2,%3,%4};"
                 :: "l"(addr), "f"(v.x), "f"(v.y), "f"(v.z), "f"(v.w) : "memory");
}
__device__ __forceinline__ unsigned pk(float a, float b) {
    __half2 h = __floats2half2_rn(a, b);
    return reinterpret_cast<unsigned&>(h);
}

// Detect int64 vs int32 for edge_index / batch (JAX x64 ambiguity).
__global__ void k_detect(const int* __restrict__ ei, const int* __restrict__ batch) {
    if (threadIdx.x != 0) return;
    int all0 = 1;
    for (int j = 0; j < 64; j++) {
        long long p = 1 + 2LL * j * 49999;
        if (ei[p] != 0) { all0 = 0; break; }
    }
    g_ei64 = all0;
    int all0b = 1;
    for (int j = 0; j < 32; j++) {
        int p = (NN - 1) - 2 * j;
        if (batch[p] != 0) { all0b = 0; break; }
    }
    g_b64 = all0b;
}

__global__ void k_zero() {
    int i = blockIdx.x * 256 + threadIdx.x;
    if (i < NN) g_cnt[i] = 0;
    if (i < NG * 32) g_pooled[i] = 0.f;
}

// ---------------- CSR build ----------------
__global__ __launch_bounds__(256) void k_hist(const void* __restrict__ ei) {
    int e = blockIdx.x * 256 + threadIdx.x;
    if (e >= NE) return;
    int dst;
    if (g_ei64) dst = (int)((const long long*)ei)[NE + e];
    else        dst = ((const int*)ei)[NE + e];
    atomicAdd(&g_cnt[dst], 1);
}

__global__ __launch_bounds__(1024) void k_scan() {
    __shared__ int s[1024];
    int tid = threadIdx.x;
    const int CH = (NN + 1023) / 1024;  // 98
    int base = tid * CH;
    int sum = 0;
    for (int i = 0; i < CH; i++) {
        int idx = base + i;
        if (idx < NN) sum += g_cnt[idx];
    }
    s[tid] = sum;
    __syncthreads();
    for (int off = 1; off < 1024; off <<= 1) {
        int v = (tid >= off) ? s[tid - off] : 0;
        __syncthreads();
        s[tid] += v;
        __syncthreads();
    }
    int run = (tid == 0) ? 0 : s[tid - 1];
    for (int i = 0; i < CH; i++) {
        int idx = base + i;
        if (idx < NN) {
            g_rowptr[idx] = run;
            g_wptr[idx] = run;
            run += g_cnt[idx];
        }
    }
    if (tid == 1023) g_rowptr[NN] = NE;
}

__global__ __launch_bounds__(256) void k_scatter(const void* __restrict__ ei) {
    int e = blockIdx.x * 256 + threadIdx.x;
    if (e >= NE) return;
    int src, dst;
    if (g_ei64) {
        const long long* p = (const long long*)ei;
        src = (int)p[e]; dst = (int)p[NE + e];
    } else {
        const int* p = (const int*)ei;
        src = p[e]; dst = p[NE + e];
    }
    int pos = atomicAdd(&g_wptr[dst], 1);
    g_srcs[pos] = src;
}

// ---------------- layer 1 node matmuls: msg1 = x@W1n (fp16), root1 = x@W1r ----
__global__ __launch_bounds__(256) void k_lin1(const float* __restrict__ x,
                                              const float* __restrict__ W1r,
                                              const float* __restrict__ W1n) {
    __shared__ float4 sWn[512];  // 128x16
    __shared__ float4 sWr[512];
    int tid = threadIdx.x;
    for (int i = tid; i < 512; i += 256) {
        sWn[i] = ((const float4*)W1n)[i];
        sWr[i] = ((const float4*)W1r)[i];
    }
    __syncthreads();
    int n = blockIdx.x * 256 + tid;
    if (n >= NN) return;
    float accn[16], accr[16];
#pragma unroll
    for (int o = 0; o < 16; o++) { accn[o] = 0.f; accr[o] = 0.f; }
    const float4* xr = (const float4*)(x + (long long)n * 128);
#pragma unroll 4
    for (int k4 = 0; k4 < 32; k4++) {
        float4 xv = xr[k4];
        float xs[4] = {xv.x, xv.y, xv.z, xv.w};
#pragma unroll
        for (int kk = 0; kk < 4; kk++) {
            int k = (k4 << 2) + kk;
#pragma unroll
            for (int o4 = 0; o4 < 4; o4++) {
                float4 wn = sWn[(k << 2) + o4];
                float4 wr = sWr[(k << 2) + o4];
                accn[(o4 << 2) + 0] += xs[kk] * wn.x;
                accn[(o4 << 2) + 1] += xs[kk] * wn.y;
                accn[(o4 << 2) + 2] += xs[kk] * wn.z;
                accn[(o4 << 2) + 3] += xs[kk] * wn.w;
                accr[(o4 << 2) + 0] += xs[kk] * wr.x;
                accr[(o4 << 2) + 1] += xs[kk] * wr.y;
                accr[(o4 << 2) + 2] += xs[kk] * wr.z;
                accr[(o4 << 2) + 3] += xs[kk] * wr.w;
            }
        }
    }
    uint4 m0, m1;
    m0.x = pk(accn[0], accn[1]);   m0.y = pk(accn[2], accn[3]);
    m0.z = pk(accn[4], accn[5]);   m0.w = pk(accn[6], accn[7]);
    m1.x = pk(accn[8], accn[9]);   m1.y = pk(accn[10], accn[11]);
    m1.z = pk(accn[12], accn[13]); m1.w = pk(accn[14], accn[15]);
    uint4* mp = (uint4*)(g_msg1 + n * 16);
    mp[0] = m0; mp[1] = m1;
    float4* r = (float4*)(g_root1 + n * 16);
#pragma unroll
    for (int o4 = 0; o4 < 4; o4++)
        r[o4] = make_float4(accr[o4 * 4], accr[o4 * 4 + 1], accr[o4 * 4 + 2], accr[o4 * 4 + 3]);
}

// ---------------- gather layer1: h1 = relu(root1 + sum msg1[src] + b1) --------
__global__ __launch_bounds__(256) void k_gather1(const float* __restrict__ b1) {
    int t = blockIdx.x * 256 + threadIdx.x;
    int n = t >> 3, q = t & 7;
    if (n >= NN) return;
    int beg = g_rowptr[n], end = g_rowptr[n + 1];
    float accx = 0.f, accy = 0.f;
    const __half2* mp = (const __half2*)g_msg1;  // row stride 8 half2
#pragma unroll 4
    for (int e = beg; e < end; e++) {
        int s = __ldg(&g_srcs[e]);
        float2 f = __half22float2(mp[s * 8 + q]);
        accx += f.x; accy += f.y;
    }
    float2 r = ((const float2*)g_root1)[n * 8 + q];
    float2 h;
    h.x = fmaxf(r.x + accx + b1[2 * q], 0.f);
    h.y = fmaxf(r.y + accy + b1[2 * q + 1], 0.f);
    ((float2*)g_h1)[n * 8 + q] = h;
}

// ---------------- node2: msg2 = h1@W2n (fp16), root2 = h1@W2r ----------------
__global__ __launch_bounds__(256) void k_node2(const float* __restrict__ W2r,
                                               const float* __restrict__ W2n) {
    __shared__ float4 sWn[128];  // 16x32
    __shared__ float4 sWr[128];
    int tid = threadIdx.x;
    if (tid < 128) { sWn[tid] = ((const float4*)W2n)[tid]; sWr[tid] = ((const float4*)W2r)[tid]; }
    __syncthreads();
    int n = blockIdx.x * 256 + tid;
    if (n >= NN) return;
    float h[16];
    const float4* hh = (const float4*)(g_h1 + n * 16);
#pragma unroll
    for (int i = 0; i < 4; i++) {
        float4 v = hh[i];
        h[i * 4 + 0] = v.x; h[i * 4 + 1] = v.y; h[i * 4 + 2] = v.z; h[i * 4 + 3] = v.w;
    }
    float acc[32];
#pragma unroll
    for (int o = 0; o < 32; o++) acc[o] = 0.f;
#pragma unroll
    for (int k = 0; k < 16; k++) {
        float hv = h[k];
#pragma unroll
        for (int o4 = 0; o4 < 8; o4++) {
            float4 w = sWn[k * 8 + o4];
            acc[o4 * 4 + 0] += hv * w.x; acc[o4 * 4 + 1] += hv * w.y;
            acc[o4 * 4 + 2] += hv * w.z; acc[o4 * 4 + 3] += hv * w.w;
        }
    }
    uint4* mp = (uint4*)(g_msg2 + n * 32);
#pragma unroll
    for (int i = 0; i < 4; i++) {
        uint4 m;
        m.x = pk(acc[i * 8 + 0], acc[i * 8 + 1]);
        m.y = pk(acc[i * 8 + 2], acc[i * 8 + 3]);
        m.z = pk(acc[i * 8 + 4], acc[i * 8 + 5]);
        m.w = pk(acc[i * 8 + 6], acc[i * 8 + 7]);
        mp[i] = m;
    }
#pragma unroll
    for (int o = 0; o < 32; o++) acc[o] = 0.f;
#pragma unroll
    for (int k = 0; k < 16; k++) {
        float hv = h[k];
#pragma unroll
        for (int o4 = 0; o4 < 8; o4++) {
            float4 w = sWr[k * 8 + o4];
            acc[o4 * 4 + 0] += hv * w.x; acc[o4 * 4 + 1] += hv * w.y;
            acc[o4 * 4 + 2] += hv * w.z; acc[o4 * 4 + 3] += hv * w.w;
        }
    }
    float4* r = (float4*)(g_root2 + n * 32);
#pragma unroll
    for (int o4 = 0; o4 < 8; o4++)
        r[o4] = make_float4(acc[o4 * 4], acc[o4 * 4 + 1], acc[o4 * 4 + 2], acc[o4 * 4 + 3]);
}

// ---------------- gather layer2: h2 = relu(root2 + sum msg2[src] + b2) --------
__global__ __launch_bounds__(256) void k_gather2(const float* __restrict__ b2) {
    int t = blockIdx.x * 256 + threadIdx.x;
    int n = t >> 3, q = t & 7;
    if (n >= NN) return;
    int beg = g_rowptr[n], end = g_rowptr[n + 1];
    float4 acc = make_float4(0.f, 0.f, 0.f, 0.f);
    const uint2* mp = (const uint2*)g_msg2;  // row stride 8 uint2 (32 halves)
#pragma unroll 4
    for (int e = beg; e < end; e++) {
        int s = __ldg(&g_srcs[e]);
        uint2 v = mp[s * 8 + q];
        __half2 h0 = reinterpret_cast<__half2&>(v.x);
        __half2 h1 = reinterpret_cast<__half2&>(v.y);
        float2 f0 = __half22float2(h0), f1 = __half22float2(h1);
        acc.x += f0.x; acc.y += f0.y; acc.z += f1.x; acc.w += f1.y;
    }
    float4 r = ((const float4*)g_root2)[n * 8 + q];
    float4 h;
    h.x = fmaxf(r.x + acc.x + b2[4 * q + 0], 0.f);
    h.y = fmaxf(r.y + acc.y + b2[4 * q + 1], 0.f);
    h.z = fmaxf(r.z + acc.z + b2[4 * q + 2], 0.f);
    h.w = fmaxf(r.w + acc.w + b2[4 * q + 3], 0.f);
    ((float4*)g_h2)[n * 8 + q] = h;
}

// ---------------- node3: msg3 = h2@W3n (fp16), root3 = h2@W3r ----------------
__global__ __launch_bounds__(256) void k_node3(const float* __restrict__ W3r,
                                               const float* __restrict__ W3n) {
    __shared__ float4 sWn[256];  // 32x32
    __shared__ float4 sWr[256];
    int tid = threadIdx.x;
    if (tid < 256) { sWn[tid] = ((const float4*)W3n)[tid]; sWr[tid] = ((const float4*)W3r)[tid]; }
    __syncthreads();
    int n = blockIdx.x * 256 + tid;
    if (n >= NN) return;
    float h[32];
    const float4* hh = (const float4*)(g_h2 + n * 32);
#pragma unroll
    for (int i = 0; i < 8; i++) {
        float4 v = hh[i];
        h[i * 4 + 0] = v.x; h[i * 4 + 1] = v.y; h[i * 4 + 2] = v.z; h[i * 4 + 3] = v.w;
    }
    float acc[32];
#pragma unroll
    for (int o = 0; o < 32; o++) acc[o] = 0.f;
#pragma unroll 8
    for (int k = 0; k < 32; k++) {
        float hv = h[k];
#pragma unroll
        for (int o4 = 0; o4 < 8; o4++) {
            float4 w = sWn[k * 8 + o4];
            acc[o4 * 4 + 0] += hv * w.x; acc[o4 * 4 + 1] += hv * w.y;
            acc[o4 * 4 + 2] += hv * w.z; acc[o4 * 4 + 3] += hv * w.w;
        }
    }
    uint4* mp = (uint4*)(g_msg3 + n * 32);
#pragma unroll
    for (int i = 0; i < 4; i++) {
        uint4 m;
        m.x = pk(acc[i * 8 + 0], acc[i * 8 + 1]);
        m.y = pk(acc[i * 8 + 2], acc[i * 8 + 3]);
        m.z = pk(acc[i * 8 + 4], acc[i * 8 + 5]);
        m.w = pk(acc[i * 8 + 6], acc[i * 8 + 7]);
        mp[i] = m;
    }
#pragma unroll
    for (int o = 0; o < 32; o++) acc[o] = 0.f;
#pragma unroll 8
    for (int k = 0; k < 32; k++) {
        float hv = h[k];
#pragma unroll
        for (int o4 = 0; o4 < 8; o4++) {
            float4 w = sWr[k * 8 + o4];
            acc[o4 * 4 + 0] += hv * w.x; acc[o4 * 4 + 1] += hv * w.y;
            acc[o4 * 4 + 2] += hv * w.z; acc[o4 * 4 + 3] += hv * w.w;
        }
    }
    float4* r = (float4*)(g_root3 + n * 32);
#pragma unroll
    for (int o4 = 0; o4 < 8; o4++)
        r[o4] = make_float4(acc[o4 * 4], acc[o4 * 4 + 1], acc[o4 * 4 + 2], acc[o4 * 4 + 3]);
}

// -------- gather layer3 fused with pool: pooled[batch[n]] += relu(...) --------
__global__ __launch_bounds__(256) void k_gather3(const float* __restrict__ b3,
                                                 const void* __restrict__ batch) {
    int t = blockIdx.x * 256 + threadIdx.x;
    int n = t >> 3, q = t & 7;
    if (n >= NN) return;
    int beg = g_rowptr[n], end = g_rowptr[n + 1];
    float4 acc = make_float4(0.f, 0.f, 0.f, 0.f);
    const uint2* mp = (const uint2*)g_msg3;
#pragma unroll 4
    for (int e = beg; e < end; e++) {
        int s = __ldg(&g_srcs[e]);
        uint2 v = mp[s * 8 + q];
        __half2 h0 = reinterpret_cast<__half2&>(v.x);
        __half2 h1 = reinterpret_cast<__half2&>(v.y);
        float2 f0 = __half22float2(h0), f1 = __half22float2(h1);
        acc.x += f0.x; acc.y += f0.y; acc.z += f1.x; acc.w += f1.y;
    }
    float4 r = ((const float4*)g_root3)[n * 8 + q];
    float4 h;
    h.x = fmaxf(r.x + acc.x + b3[4 * q + 0], 0.f);
    h.y = fmaxf(r.y + acc.y + b3[4 * q + 1], 0.f);
    h.z = fmaxf(r.z + acc.z + b3[4 * q + 2], 0.f);
    h.w = fmaxf(r.w + acc.w + b3[4 * q + 3], 0.f);
    int g;
    if (g_b64) g = (int)((const long long*)batch)[n];
    else       g = ((const int*)batch)[n];
    red4(g_pooled + g * 32 + q * 4, h);
}

// ---------------- out = pooled @ Wlin + blin ----------------
__global__ __launch_bounds__(64) void k_final(const float* __restrict__ Wlin,
                                              const float* __restrict__ blin,
                                              float* __restrict__ out) {
    __shared__ float sW[32 * 64];
    int tid = threadIdx.x;
    for (int i = tid; i < 2048; i += 64) sW[i] = Wlin[i];
    __syncthreads();
    int g = blockIdx.x;
    float acc = blin[tid];
    const float* p = g_pooled + g * 32;
#pragma unroll
    for (int k = 0; k < 32; k++) acc += p[k] * sW[k * 64 + tid];
    out[g * 64 + tid] = acc;
}

// ---------------- launch ----------------
extern "C" void kernel_launch(void* const* d_in, const int* in_sizes, int n_in,
                              void* d_out, int out_size) {
    const float* x     = (const float*)d_in[0];
    const void*  ei    = d_in[1];
    const void*  batch = d_in[2];
    const float* W1r = (const float*)d_in[3];
    const float* W1n = (const float*)d_in[4];
    const float* b1  = (const float*)d_in[5];
    const float* W2r = (const float*)d_in[6];
    const float* W2n = (const float*)d_in[7];
    const float* b2  = (const float*)d_in[8];
    const float* W3r = (const float*)d_in[9];
    const float* W3n = (const float*)d_in[10];
    const float* b3  = (const float*)d_in[11];
    const float* Wlin = (const float*)d_in[12];
    const float* blin = (const float*)d_in[13];
    float* out = (float*)d_out;

    const int NODE_BLKS = (NN + 255) / 256;       // 391
    const int EDGE_BLKS = (NE + 255) / 256;       // 12500
    const int GATH_BLKS = (NN * 8 + 255) / 256;   // 3125

    k_detect<<<1, 1>>>((const int*)ei, (const int*)batch);
    k_zero<<<NODE_BLKS, 256>>>();
    k_hist<<<EDGE_BLKS, 256>>>(ei);
    k_scan<<<1, 1024>>>();
    k_scatter<<<EDGE_BLKS, 256>>>(ei);
    k_lin1<<<NODE_BLKS, 256>>>(x, W1r, W1n);
    k_gather1<<<GATH_BLKS, 256>>>(b1);
    k_node2<<<NODE_BLKS, 256>>>(W2r, W2n);
    k_gather2<<<GATH_BLKS, 256>>>(b2);
    k_node3<<<NODE_BLKS, 256>>>(W3r, W3n);
    k_gather3<<<GATH_BLKS, 256>>>(b3, batch);
    k_final<<<NG, 64>>>(Wlin, blin, out);
}

// round 3
// speedup vs baseline: 1.6685x; 1.6685x over previous
#include <cuda_runtime.h>
#include <cuda_fp16.h>

#define NN 100000
#define NE 3200000
#define NG 1000
#define SCAN_BLK 1024
#define SCAN_NBLK ((NN + SCAN_BLK - 1) / SCAN_BLK)   // 98

// ---------------- scratch (device globals) ----------------
__device__ __align__(16) __half g_msg1[NN * 16];
__device__ __align__(16) float  g_root1[NN * 16];
__device__ __align__(16) float  g_h1[NN * 16];
__device__ __align__(16) __half g_msg2[NN * 32];
__device__ __align__(16) float  g_root2[NN * 32];
__device__ __align__(16) float  g_h2[NN * 32];
__device__ __align__(16) __half g_msg3[NN * 32];
__device__ __align__(16) float  g_root3[NN * 32];
__device__ __align__(16) float  g_pooled[NG * 32];
__device__ int g_cnt[NN];
__device__ int g_rowptr[NN + 1];
__device__ int g_wptr[NN];
__device__ int g_srcs[NE];
__device__ int g_bsum[SCAN_NBLK];
__device__ int g_ei64;
__device__ int g_b64;

// ---------------- helpers ----------------
__device__ __forceinline__ void red4(float* addr, float4 v) {
    asm volatile("red.global.add.v4.f32 [%0], {%1,%2,%3,%4};"
                 :: "l"(addr), "f"(v.x), "f"(v.y), "f"(v.z), "f"(v.w) : "memory");
}
__device__ __forceinline__ unsigned pk(float a, float b) {
    __half2 h = __floats2half2_rn(a, b);
    return reinterpret_cast<unsigned&>(h);
}

// Detect int64 vs int32 for edge_index / batch (JAX x64 ambiguity).
__global__ void k_detect(const int* __restrict__ ei, const int* __restrict__ batch) {
    if (threadIdx.x != 0) return;
    int all0 = 1;
    for (int j = 0; j < 64; j++) {
        long long p = 1 + 2LL * j * 49999;
        if (ei[p] != 0) { all0 = 0; break; }
    }
    g_ei64 = all0;
    int all0b = 1;
    for (int j = 0; j < 32; j++) {
        int p = (NN - 1) - 2 * j;
        if (batch[p] != 0) { all0b = 0; break; }
    }
    g_b64 = all0b;
}

__global__ void k_zero() {
    int i = blockIdx.x * 256 + threadIdx.x;
    if (i < NN) g_cnt[i] = 0;
    if (i < NG * 32) g_pooled[i] = 0.f;
}

// ---------------- CSR build ----------------
__global__ __launch_bounds__(256) void k_hist(const void* __restrict__ ei) {
    int e = blockIdx.x * 256 + threadIdx.x;
    if (e >= NE) return;
    int dst;
    if (g_ei64) dst = (int)((const long long*)ei)[NE + e];
    else        dst = ((const int*)ei)[NE + e];
    atomicAdd(&g_cnt[dst], 1);
}

// Pass 1: per-block exclusive scan of g_cnt into g_rowptr; block totals to g_bsum.
__global__ __launch_bounds__(SCAN_BLK) void k_scan1() {
    __shared__ int warpsum[32];
    int tid = threadIdx.x;
    int i = blockIdx.x * SCAN_BLK + tid;
    int val = (i < NN) ? g_cnt[i] : 0;
    int lane = tid & 31, wid = tid >> 5;
    // intra-warp inclusive scan
    int inc = val;
#pragma unroll
    for (int off = 1; off < 32; off <<= 1) {
        int v = __shfl_up_sync(0xffffffffu, inc, off);
        if (lane >= off) inc += v;
    }
    if (lane == 31) warpsum[wid] = inc;
    __syncthreads();
    if (wid == 0) {
        int ws = (lane < 32) ? warpsum[lane] : 0;
#pragma unroll
        for (int off = 1; off < 32; off <<= 1) {
            int v = __shfl_up_sync(0xffffffffu, ws, off);
            if (lane >= off) ws += v;
        }
        warpsum[lane] = ws;
    }
    __syncthreads();
    int wofs = (wid == 0) ? 0 : warpsum[wid - 1];
    int excl = wofs + inc - val;
    if (i < NN) g_rowptr[i] = excl;
    if (tid == SCAN_BLK - 1) g_bsum[blockIdx.x] = wofs + inc;
}

// Pass 2: exclusive-scan the 98 block sums (one block, 128 threads).
__global__ __launch_bounds__(128) void k_scan2() {
    __shared__ int s[128];
    int tid = threadIdx.x;
    int val = (tid < SCAN_NBLK) ? g_bsum[tid] : 0;
    s[tid] = val;
    __syncthreads();
#pragma unroll
    for (int off = 1; off < 128; off <<= 1) {
        int v = (tid >= off) ? s[tid - off] : 0;
        __syncthreads();
        s[tid] += v;
        __syncthreads();
    }
    if (tid < SCAN_NBLK) g_bsum[tid] = s[tid] - val;  // exclusive
}

// Pass 3: add block offsets; mirror into wptr; set rowptr[NN].
__global__ __launch_bounds__(SCAN_BLK) void k_scan3() {
    int i = blockIdx.x * SCAN_BLK + threadIdx.x;
    if (i == 0) g_rowptr[NN] = NE;
    if (i >= NN) return;
    int r = g_rowptr[i] + g_bsum[blockIdx.x];
    g_rowptr[i] = r;
    g_wptr[i] = r;
}

__global__ __launch_bounds__(256) void k_scatter(const void* __restrict__ ei) {
    int e = blockIdx.x * 256 + threadIdx.x;
    if (e >= NE) return;
    int src, dst;
    if (g_ei64) {
        const long long* p = (const long long*)ei;
        src = (int)p[e]; dst = (int)p[NE + e];
    } else {
        const int* p = (const int*)ei;
        src = p[e]; dst = p[NE + e];
    }
    int pos = atomicAdd(&g_wptr[dst], 1);
    g_srcs[pos] = src;
}

// ---------------- layer 1 node matmuls: msg1 = x@W1n (fp16), root1 = x@W1r ----
__global__ __launch_bounds__(256) void k_lin1(const float* __restrict__ x,
                                              const float* __restrict__ W1r,
                                              const float* __restrict__ W1n) {
    __shared__ float4 sWn[512];  // 128x16
    __shared__ float4 sWr[512];
    int tid = threadIdx.x;
    for (int i = tid; i < 512; i += 256) {
        sWn[i] = ((const float4*)W1n)[i];
        sWr[i] = ((const float4*)W1r)[i];
    }
    __syncthreads();
    int n = blockIdx.x * 256 + tid;
    if (n >= NN) return;
    float accn[16], accr[16];
#pragma unroll
    for (int o = 0; o < 16; o++) { accn[o] = 0.f; accr[o] = 0.f; }
    const float4* xr = (const float4*)(x + (long long)n * 128);
#pragma unroll 4
    for (int k4 = 0; k4 < 32; k4++) {
        float4 xv = xr[k4];
        float xs[4] = {xv.x, xv.y, xv.z, xv.w};
#pragma unroll
        for (int kk = 0; kk < 4; kk++) {
            int k = (k4 << 2) + kk;
#pragma unroll
            for (int o4 = 0; o4 < 4; o4++) {
                float4 wn = sWn[(k << 2) + o4];
                float4 wr = sWr[(k << 2) + o4];
                accn[(o4 << 2) + 0] += xs[kk] * wn.x;
                accn[(o4 << 2) + 1] += xs[kk] * wn.y;
                accn[(o4 << 2) + 2] += xs[kk] * wn.z;
                accn[(o4 << 2) + 3] += xs[kk] * wn.w;
                accr[(o4 << 2) + 0] += xs[kk] * wr.x;
                accr[(o4 << 2) + 1] += xs[kk] * wr.y;
                accr[(o4 << 2) + 2] += xs[kk] * wr.z;
                accr[(o4 << 2) + 3] += xs[kk] * wr.w;
            }
        }
    }
    uint4 m0, m1;
    m0.x = pk(accn[0], accn[1]);   m0.y = pk(accn[2], accn[3]);
    m0.z = pk(accn[4], accn[5]);   m0.w = pk(accn[6], accn[7]);
    m1.x = pk(accn[8], accn[9]);   m1.y = pk(accn[10], accn[11]);
    m1.z = pk(accn[12], accn[13]); m1.w = pk(accn[14], accn[15]);
    uint4* mp = (uint4*)(g_msg1 + n * 16);
    mp[0] = m0; mp[1] = m1;
    float4* r = (float4*)(g_root1 + n * 16);
#pragma unroll
    for (int o4 = 0; o4 < 4; o4++)
        r[o4] = make_float4(accr[o4 * 4], accr[o4 * 4 + 1], accr[o4 * 4 + 2], accr[o4 * 4 + 3]);
}

// ---------------- gather layer1: h1 = relu(root1 + sum msg1[src] + b1) --------
__global__ __launch_bounds__(256) void k_gather1(const float* __restrict__ b1) {
    int t = blockIdx.x * 256 + threadIdx.x;
    int n = t >> 3, q = t & 7;
    if (n >= NN) return;
    int beg = g_rowptr[n], end = g_rowptr[n + 1];
    float accx = 0.f, accy = 0.f;
    const __half2* mp = (const __half2*)g_msg1;  // row stride 8 half2
#pragma unroll 4
    for (int e = beg; e < end; e++) {
        int s = __ldg(&g_srcs[e]);
        float2 f = __half22float2(mp[s * 8 + q]);
        accx += f.x; accy += f.y;
    }
    float2 r = ((const float2*)g_root1)[n * 8 + q];
    float2 h;
    h.x = fmaxf(r.x + accx + b1[2 * q], 0.f);
    h.y = fmaxf(r.y + accy + b1[2 * q + 1], 0.f);
    ((float2*)g_h1)[n * 8 + q] = h;
}

// ---------------- node2: msg2 = h1@W2n (fp16), root2 = h1@W2r ----------------
__global__ __launch_bounds__(256) void k_node2(const float* __restrict__ W2r,
                                               const float* __restrict__ W2n) {
    __shared__ float4 sWn[128];  // 16x32
    __shared__ float4 sWr[128];
    int tid = threadIdx.x;
    if (tid < 128) { sWn[tid] = ((const float4*)W2n)[tid]; sWr[tid] = ((const float4*)W2r)[tid]; }
    __syncthreads();
    int n = blockIdx.x * 256 + tid;
    if (n >= NN) return;
    float h[16];
    const float4* hh = (const float4*)(g_h1 + n * 16);
#pragma unroll
    for (int i = 0; i < 4; i++) {
        float4 v = hh[i];
        h[i * 4 + 0] = v.x; h[i * 4 + 1] = v.y; h[i * 4 + 2] = v.z; h[i * 4 + 3] = v.w;
    }
    float acc[32];
#pragma unroll
    for (int o = 0; o < 32; o++) acc[o] = 0.f;
#pragma unroll
    for (int k = 0; k < 16; k++) {
        float hv = h[k];
#pragma unroll
        for (int o4 = 0; o4 < 8; o4++) {
            float4 w = sWn[k * 8 + o4];
            acc[o4 * 4 + 0] += hv * w.x; acc[o4 * 4 + 1] += hv * w.y;
            acc[o4 * 4 + 2] += hv * w.z; acc[o4 * 4 + 3] += hv * w.w;
        }
    }
    uint4* mp = (uint4*)(g_msg2 + n * 32);
#pragma unroll
    for (int i = 0; i < 4; i++) {
        uint4 m;
        m.x = pk(acc[i * 8 + 0], acc[i * 8 + 1]);
        m.y = pk(acc[i * 8 + 2], acc[i * 8 + 3]);
        m.z = pk(acc[i * 8 + 4], acc[i * 8 + 5]);
        m.w = pk(acc[i * 8 + 6], acc[i * 8 + 7]);
        mp[i] = m;
    }
#pragma unroll
    for (int o = 0; o < 32; o++) acc[o] = 0.f;
#pragma unroll
    for (int k = 0; k < 16; k++) {
        float hv = h[k];
#pragma unroll
        for (int o4 = 0; o4 < 8; o4++) {
            float4 w = sWr[k * 8 + o4];
            acc[o4 * 4 + 0] += hv * w.x; acc[o4 * 4 + 1] += hv * w.y;
            acc[o4 * 4 + 2] += hv * w.z; acc[o4 * 4 + 3] += hv * w.w;
        }
    }
    float4* r = (float4*)(g_root2 + n * 32);
#pragma unroll
    for (int o4 = 0; o4 < 8; o4++)
        r[o4] = make_float4(acc[o4 * 4], acc[o4 * 4 + 1], acc[o4 * 4 + 2], acc[o4 * 4 + 3]);
}

// ---------------- gather layer2: h2 = relu(root2 + sum msg2[src] + b2) --------
__global__ __launch_bounds__(256) void k_gather2(const float* __restrict__ b2) {
    int t = blockIdx.x * 256 + threadIdx.x;
    int n = t >> 3, q = t & 7;
    if (n >= NN) return;
    int beg = g_rowptr[n], end = g_rowptr[n + 1];
    float4 acc = make_float4(0.f, 0.f, 0.f, 0.f);
    const uint2* mp = (const uint2*)g_msg2;  // row stride 8 uint2 (32 halves)
#pragma unroll 4
    for (int e = beg; e < end; e++) {
        int s = __ldg(&g_srcs[e]);
        uint2 v = mp[s * 8 + q];
        __half2 h0 = reinterpret_cast<__half2&>(v.x);
        __half2 h1 = reinterpret_cast<__half2&>(v.y);
        float2 f0 = __half22float2(h0), f1 = __half22float2(h1);
        acc.x += f0.x; acc.y += f0.y; acc.z += f1.x; acc.w += f1.y;
    }
    float4 r = ((const float4*)g_root2)[n * 8 + q];
    float4 h;
    h.x = fmaxf(r.x + acc.x + b2[4 * q + 0], 0.f);
    h.y = fmaxf(r.y + acc.y + b2[4 * q + 1], 0.f);
    h.z = fmaxf(r.z + acc.z + b2[4 * q + 2], 0.f);
    h.w = fmaxf(r.w + acc.w + b2[4 * q + 3], 0.f);
    ((float4*)g_h2)[n * 8 + q] = h;
}

// ---------------- node3: msg3 = h2@W3n (fp16), root3 = h2@W3r ----------------
__global__ __launch_bounds__(256) void k_node3(const float* __restrict__ W3r,
                                               const float* __restrict__ W3n) {
    __shared__ float4 sWn[256];  // 32x32
    __shared__ float4 sWr[256];
    int tid = threadIdx.x;
    if (tid < 256) { sWn[tid] = ((const float4*)W3n)[tid]; sWr[tid] = ((const float4*)W3r)[tid]; }
    __syncthreads();
    int n = blockIdx.x * 256 + tid;
    if (n >= NN) return;
    float h[32];
    const float4* hh = (const float4*)(g_h2 + n * 32);
#pragma unroll
    for (int i = 0; i < 8; i++) {
        float4 v = hh[i];
        h[i * 4 + 0] = v.x; h[i * 4 + 1] = v.y; h[i * 4 + 2] = v.z; h[i * 4 + 3] = v.w;
    }
    float acc[32];
#pragma unroll
    for (int o = 0; o < 32; o++) acc[o] = 0.f;
#pragma unroll 8
    for (int k = 0; k < 32; k++) {
        float hv = h[k];
#pragma unroll
        for (int o4 = 0; o4 < 8; o4++) {
            float4 w = sWn[k * 8 + o4];
            acc[o4 * 4 + 0] += hv * w.x; acc[o4 * 4 + 1] += hv * w.y;
            acc[o4 * 4 + 2] += hv * w.z; acc[o4 * 4 + 3] += hv * w.w;
        }
    }
    uint4* mp = (uint4*)(g_msg3 + n * 32);
#pragma unroll
    for (int i = 0; i < 4; i++) {
        uint4 m;
        m.x = pk(acc[i * 8 + 0], acc[i * 8 + 1]);
        m.y = pk(acc[i * 8 + 2], acc[i * 8 + 3]);
        m.z = pk(acc[i * 8 + 4], acc[i * 8 + 5]);
        m.w = pk(acc[i * 8 + 6], acc[i * 8 + 7]);
        mp[i] = m;
    }
#pragma unroll
    for (int o = 0; o < 32; o++) acc[o] = 0.f;
#pragma unroll 8
    for (int k = 0; k < 32; k++) {
        float hv = h[k];
#pragma unroll
        for (int o4 = 0; o4 < 8; o4++) {
            float4 w = sWr[k * 8 + o4];
            acc[o4 * 4 + 0] += hv * w.x; acc[o4 * 4 + 1] += hv * w.y;
            acc[o4 * 4 + 2] += hv * w.z; acc[o4 * 4 + 3] += hv * w.w;
        }
    }
    float4* r = (float4*)(g_root3 + n * 32);
#pragma unroll
    for (int o4 = 0; o4 < 8; o4++)
        r[o4] = make_float4(acc[o4 * 4], acc[o4 * 4 + 1], acc[o4 * 4 + 2], acc[o4 * 4 + 3]);
}

// -------- gather layer3 fused with pool: pooled[batch[n]] += relu(...) --------
__global__ __launch_bounds__(256) void k_gather3(const float* __restrict__ b3,
                                                 const void* __restrict__ batch) {
    int t = blockIdx.x * 256 + threadIdx.x;
    int n = t >> 3, q = t & 7;
    if (n >= NN) return;
    int beg = g_rowptr[n], end = g_rowptr[n + 1];
    float4 acc = make_float4(0.f, 0.f, 0.f, 0.f);
    const uint2* mp = (const uint2*)g_msg3;
#pragma unroll 4
    for (int e = beg; e < end; e++) {
        int s = __ldg(&g_srcs[e]);
        uint2 v = mp[s * 8 + q];
        __half2 h0 = reinterpret_cast<__half2&>(v.x);
        __half2 h1 = reinterpret_cast<__half2&>(v.y);
        float2 f0 = __half22float2(h0), f1 = __half22float2(h1);
        acc.x += f0.x; acc.y += f0.y; acc.z += f1.x; acc.w += f1.y;
    }
    float4 r = ((const float4*)g_root3)[n * 8 + q];
    float4 h;
    h.x = fmaxf(r.x + acc.x + b3[4 * q + 0], 0.f);
    h.y = fmaxf(r.y + acc.y + b3[4 * q + 1], 0.f);
    h.z = fmaxf(r.z + acc.z + b3[4 * q + 2], 0.f);
    h.w = fmaxf(r.w + acc.w + b3[4 * q + 3], 0.f);
    int g;
    if (g_b64) g = (int)((const long long*)batch)[n];
    else       g = ((const int*)batch)[n];
    red4(g_pooled + g * 32 + q * 4, h);
}

// ---------------- out = pooled @ Wlin + blin ----------------
__global__ __launch_bounds__(64) void k_final(const float* __restrict__ Wlin,
                                              const float* __restrict__ blin,
                                              float* __restrict__ out) {
    __shared__ float sW[32 * 64];
    int tid = threadIdx.x;
    for (int i = tid; i < 2048; i += 64) sW[i] = Wlin[i];
    __syncthreads();
    int g = blockIdx.x;
    float acc = blin[tid];
    const float* p = g_pooled + g * 32;
#pragma unroll
    for (int k = 0; k < 32; k++) acc += p[k] * sW[k * 64 + tid];
    out[g * 64 + tid] = acc;
}

// ---------------- launch ----------------
extern "C" void kernel_launch(void* const* d_in, const int* in_sizes, int n_in,
                              void* d_out, int out_size) {
    const float* x     = (const float*)d_in[0];
    const void*  ei    = d_in[1];
    const void*  batch = d_in[2];
    const float* W1r = (const float*)d_in[3];
    const float* W1n = (const float*)d_in[4];
    const float* b1  = (const float*)d_in[5];
    const float* W2r = (const float*)d_in[6];
    const float* W2n = (const float*)d_in[7];
    const float* b2  = (const float*)d_in[8];
    const float* W3r = (const float*)d_in[9];
    const float* W3n = (const float*)d_in[10];
    const float* b3  = (const float*)d_in[11];
    const float* Wlin = (const float*)d_in[12];
    const float* blin = (const float*)d_in[13];
    float* out = (float*)d_out;

    const int NODE_BLKS = (NN + 255) / 256;       // 391
    const int EDGE_BLKS = (NE + 255) / 256;       // 12500
    const int GATH_BLKS = (NN * 8 + 255) / 256;   // 3125

    k_detect<<<1, 1>>>((const int*)ei, (const int*)batch);
    k_zero<<<NODE_BLKS, 256>>>();
    k_hist<<<EDGE_BLKS, 256>>>(ei);
    k_scan1<<<SCAN_NBLK, SCAN_BLK>>>();
    k_scan2<<<1, 128>>>();
    k_scan3<<<SCAN_NBLK, SCAN_BLK>>>();
    k_scatter<<<EDGE_BLKS, 256>>>(ei);
    k_lin1<<<NODE_BLKS, 256>>>(x, W1r, W1n);
    k_gather1<<<GATH_BLKS, 256>>>(b1);
    k_node2<<<NODE_BLKS, 256>>>(W2r, W2n);
    k_gather2<<<GATH_BLKS, 256>>>(b2);
    k_node3<<<NODE_BLKS, 256>>>(W3r, W3n);
    k_gather3<<<GATH_BLKS, 256>>>(b3, batch);
    k_final<<<NG, 64>>>(Wlin, blin, out);
}